// round 10
// baseline (speedup 1.0000x reference)
#include <cuda_runtime.h>
#include <cuda_bf16.h>
#include <cstdint>

#define NB 4
#define D0 64
#define C1 64
#define C2 128
#define DS 32
#define NCELL (NB*DS*DS*DS)   // 131072

// ---------------- scratch (device globals) ----------------------------------
__device__ float          g_xds [NCELL*C1];     // downsampled x*m (fp32, skip)
__device__ float          g_m2  [NCELL];
__device__ __nv_bfloat16  g_h1hi[NCELL*C1];     // conv1 input hi
__device__ __nv_bfloat16  g_h1lo[NCELL*C1];     // conv1 input lo
__device__ __nv_bfloat16  g_c1hi[NCELL*C2];     // conv2 input hi
__device__ __nv_bfloat16  g_c1lo[NCELL*C2];     // conv2 input lo
__device__ unsigned char  g_wA1[27*1*32768];    // conv1 B tiles (hi+lo), smem layout
__device__ unsigned char  g_wA2[27*2*32768];    // conv2 B tiles
__device__ int            g_mask_mode;

// ---------------- helpers ----------------------------------------------------
__device__ __forceinline__ uint32_t smem_u32(const void* p){
    uint32_t a;
    asm("{ .reg .u64 t; cvta.to.shared.u64 t, %1; cvt.u32.u64 %0, t; }" : "=r"(a) : "l"(p));
    return a;
}
__device__ __forceinline__ void cpa16z(uint32_t dst, const void* src, bool ok){
    int sz = ok ? 16 : 0;
    asm volatile("cp.async.cg.shared.global [%0], [%1], 16, %2;" :: "r"(dst), "l"(src), "r"(sz));
}
__device__ __forceinline__ void cpa_commit(){ asm volatile("cp.async.commit_group;"); }

__device__ __forceinline__ void ldsm4(uint32_t* r, uint32_t addr){
    asm volatile("ldmatrix.sync.aligned.m8n8.x4.shared.b16 {%0,%1,%2,%3}, [%4];"
        : "=r"(r[0]), "=r"(r[1]), "=r"(r[2]), "=r"(r[3]) : "r"(addr));
}
__device__ __forceinline__ void mma16816(float* d, const uint32_t* a, const uint32_t* b){
    asm volatile("mma.sync.aligned.m16n8k16.row.col.f32.bf16.bf16.f32 "
        "{%0,%1,%2,%3}, {%4,%5,%6,%7}, {%8,%9}, {%0,%1,%2,%3};"
        : "+f"(d[0]), "+f"(d[1]), "+f"(d[2]), "+f"(d[3])
        : "r"(a[0]), "r"(a[1]), "r"(a[2]), "r"(a[3]), "r"(b[0]), "r"(b[1]));
}
// XOR swizzle for [row][128B] tiles (conflict-free ldmatrix + 16B stores)
__device__ __host__ __forceinline__ uint32_t swz(uint32_t row, uint32_t bytecol){
    uint32_t off = row*128u + bytecol;
    return off ^ ((off >> 3) & 0x70u);
}

// ---------------- mask dtype detection ---------------------------------------
__global__ void k_detect(const unsigned int* __restrict__ m, int nwords)
{
    if (threadIdx.x == 0 && blockIdx.x == 0) {
        int mode = 0;
        for (int i = 0; i < nwords; i++) {
            unsigned w = m[i];
            if (w == 0u) continue;
            if (w == 1u)               mode = 0;
            else if (w == 0x3F800000u) mode = 0;
            else                       mode = 2;
            break;
        }
        g_mask_mode = mode;
    }
}
__device__ __forceinline__ bool mask_at(const void* m, long v, int mode)
{
    if (mode == 2) return ((const unsigned char*)m)[v] != 0;
    return ((const unsigned int*)m)[v] != 0u;
}

// ---------------- weight prep: transpose + hi/lo split + smem layout ---------
__global__ void k_prep_w(const float* __restrict__ w, unsigned char* __restrict__ dst, int CIN)
{
    const int total = 27*CIN*128;
    for (int e = blockIdx.x*blockDim.x + threadIdx.x; e < total; e += gridDim.x*blockDim.x) {
        const int t   = e / (CIN*128);
        const int rem = e - t*(CIN*128);
        const int ci  = rem >> 7;
        const int co  = rem & 127;
        const float wv = w[e];
        const __nv_bfloat16 hi = __float2bfloat16(wv);
        const __nv_bfloat16 lo = __float2bfloat16(wv - __bfloat162float(hi));
        const int kc = ci >> 6, cil = ci & 63;
        const int stage = t*(CIN >> 6) + kc;
        const uint32_t off = swz((uint32_t)co, (uint32_t)cil*2u);
        unsigned char* base = dst + (long)stage*32768;
        *(__nv_bfloat16*)(base + off)         = hi;
        *(__nv_bfloat16*)(base + 16384 + off) = lo;
    }
}

// ---------------- K1: LN1+affine+SiLU+mask + 2x downsample -------------------
__global__ void __launch_bounds__(256)
k_ln_ds(const float* __restrict__ feats, const void* __restrict__ mask,
        const float* __restrict__ gamma, const float* __restrict__ beta)
{
    const int bid = blockIdx.x;
    const int dx = bid & 31, dy = (bid >> 5) & 31, dz = (bid >> 10) & 31, b = bid >> 15;
    const int tid = threadIdx.x;
    const int s   = tid >> 5;
    const int ln  = tid & 31;
    const int mode = g_mask_mode;

    __shared__ float sh_h[8*64];
    __shared__ float sh_x[8*64];
    __shared__ int   sh_c[8];

    const int z = 2*dz + (s >> 2);
    const int y = 2*dy + ((s >> 1) & 1);
    const int x = 2*dx + (s & 1);
    const long v = (((long)b*D0 + z)*D0 + y)*D0 + x;
    const bool act = mask_at(mask, v, mode);

    const float2 xv = *(const float2*)(feats + v*C1 + ln*2);
    float a = xv.x + xv.y;
    float q = xv.x*xv.x + xv.y*xv.y;
    #pragma unroll
    for (int o = 16; o > 0; o >>= 1) {
        a += __shfl_xor_sync(0xffffffffu, a, o);
        q += __shfl_xor_sync(0xffffffffu, q, o);
    }
    const float mu  = a * (1.f/64.f);
    const float var = q * (1.f/64.f) - mu*mu;
    const float rs  = rsqrtf(var + 1e-6f);

    const float2 g  = *(const float2*)(gamma + ln*2);
    const float2 be = *(const float2*)(beta  + ln*2);
    float h0 = (xv.x - mu)*rs*g.x + be.x;
    float h1 = (xv.y - mu)*rs*g.y + be.y;
    h0 = h0 / (1.f + __expf(-h0));
    h1 = h1 / (1.f + __expf(-h1));

    sh_h[s*64 + ln*2    ] = act ? h0 : 0.f;
    sh_h[s*64 + ln*2 + 1] = act ? h1 : 0.f;
    sh_x[s*64 + ln*2    ] = act ? xv.x : 0.f;
    sh_x[s*64 + ln*2 + 1] = act ? xv.y : 0.f;
    if (ln == 0) sh_c[s] = act ? 1 : 0;
    __syncthreads();

    if (tid < 64) {
        float hs = 0.f, xs = 0.f;
        int cnt = 0;
        #pragma unroll
        for (int k = 0; k < 8; k++) {
            hs += sh_h[k*64 + tid];
            xs += sh_x[k*64 + tid];
            cnt += sh_c[k];
        }
        const float inv = 1.f / (float)max(cnt, 1);
        const float hv = hs * inv;
        const __nv_bfloat16 hhi = __float2bfloat16(hv);
        const __nv_bfloat16 hlo = __float2bfloat16(hv - __bfloat162float(hhi));
        g_h1hi[(long)bid*C1 + tid] = hhi;
        g_h1lo[(long)bid*C1 + tid] = hlo;
        g_xds [(long)bid*C1 + tid] = xs * inv;
        if (tid == 0) g_m2[bid] = (cnt > 0) ? 1.f : 0.f;
    }
}

// ---------------- conv via mma.sync (split-bf16 3-term) ----------------------
// Block 512 thr / 16 warps. Tile: 256 voxels (8 dy rows x 32 x) x 128 cout.
// Warp (wm 0..7, wn 0..1): 32 vox x 64 co; frags: 2 m x 8 n of m16n8k16.
// Stage (tap, kc): A [256 vox][64 ci] hi+lo (64KB, zfill halos) +
//                  B [128 co ][64 ci] hi+lo (32KB straight copy).
template<int CIN, bool FUSE_LN>
__global__ void __launch_bounds__(512, 1)
k_convmma(const __nv_bfloat16* __restrict__ inhi, const __nv_bfloat16* __restrict__ inlo,
          const unsigned char* __restrict__ wA, const float* __restrict__ bias,
          const float* __restrict__ m2,
          float* __restrict__ outf,
          __nv_bfloat16* __restrict__ outhi, __nv_bfloat16* __restrict__ outlo)
{
    constexpr int NKC = CIN / 64;
    constexpr int NS  = 27 * NKC;
    constexpr uint32_t STG = 98304u;   // 64KB A + 32KB B

    extern __shared__ char smraw[];
    const uint32_t sb0 = smem_u32(smraw);
    const uint32_t BUF = (sb0 + 1023) & ~1023u;
    float* s_red = (float*)(smraw + (BUF - sb0));   // epilogue reuse (guarded by syncs)

    const int tid  = threadIdx.x;
    const int lane = tid & 31;
    const int w    = tid >> 5;
    const int wm   = w >> 1;          // 0..7 (dy row)
    const int wn   = w & 1;           // 0..1
    const int dy0  = blockIdx.x * 8;
    const int dz   = blockIdx.y;
    const int b    = blockIdx.z;

    float acc[2][8][4];
    #pragma unroll
    for (int mf = 0; mf < 2; mf++)
        #pragma unroll
        for (int nf = 0; nf < 8; nf++)
            #pragma unroll
            for (int k = 0; k < 4; k++) acc[mf][nf][k] = 0.f;

    // ---- stage copier: 12 x 16B chunks per thread ----
    auto stage_copy = [&](int s, int p){
        const int t  = s / NKC;
        const int kc = s - t*NKC;
        const int kd = t / 9;
        const int r9 = t - kd*9;
        const int kh = r9 / 3;
        const int kw = r9 - kh*3;
        const int z  = dz + kd - 1;
        const bool zok = (unsigned)z < DS;
        const uint32_t base = BUF + (uint32_t)p * STG;
        #pragma unroll
        for (int i = 0; i < 12; i++) {
            const int flat = tid + i*512;            // 0..6143 (16B units)
            if (flat < 4096) {                       // A input tiles (hi, lo)
                const int half = flat >> 11;
                const int f    = flat & 2047;
                const int vox  = f >> 3;             // 0..255
                const int seg  = f & 7;
                const int r    = vox >> 5;           // 0..7
                const int x    = vox & 31;
                const int y    = dy0 + r + kh - 1;
                const int xx   = x + kw - 1;
                const bool ok  = zok && ((unsigned)y < DS) && ((unsigned)xx < DS);
                const long cell = ok ? ((((long)b*DS + z)*DS + y)*DS + xx) : 0;
                const __nv_bfloat16* src =
                    (half ? inlo : inhi) + cell*CIN + kc*64 + seg*8;
                cpa16z(base + (uint32_t)half*32768u + swz((uint32_t)vox, (uint32_t)seg*16u),
                       src, ok);
            } else {                                  // B weight tiles: straight 32KB
                const int f = flat - 4096;
                cpa16z(base + 65536u + (uint32_t)f*16u,
                       wA + (long)s*32768 + (long)f*16, true);
            }
        }
        cpa_commit();
    };

    stage_copy(0, 0);

    for (int s = 0; s < NS; s++) {
        if (s + 1 < NS) {
            stage_copy(s + 1, (s + 1) & 1);
            asm volatile("cp.async.wait_group 1;");
        } else {
            asm volatile("cp.async.wait_group 0;");
        }
        __syncthreads();

        const uint32_t Ab = BUF + (uint32_t)(s & 1)*STG;
        const uint32_t Bb = Ab + 65536u;

        #pragma unroll
        for (int ks = 0; ks < 4; ks++) {
            const uint32_t colb = (uint32_t)(ks*16 + ((lane >> 4) & 1)*8) * 2u;
            uint32_t a_hi[2][4], a_lo[2][4];
            #pragma unroll
            for (int mf = 0; mf < 2; mf++) {
                const uint32_t row = (uint32_t)(wm*32 + mf*16 + (lane & 15));
                const uint32_t ad = Ab + swz(row, colb);
                ldsm4(a_hi[mf], ad);
                ldsm4(a_lo[mf], ad + 32768u);
            }
            #pragma unroll
            for (int nf2 = 0; nf2 < 4; nf2++) {
                const uint32_t row = (uint32_t)(wn*64 + nf2*16 + (lane & 15));
                const uint32_t ad = Bb + swz(row, colb);
                uint32_t bh[4], bl[4];
                ldsm4(bh, ad);
                ldsm4(bl, ad + 16384u);
                uint32_t b0h[2] = {bh[0], bh[2]}, b1h[2] = {bh[1], bh[3]};
                uint32_t b0l[2] = {bl[0], bl[2]}, b1l[2] = {bl[1], bl[3]};
                #pragma unroll
                for (int mf = 0; mf < 2; mf++) {
                    mma16816(acc[mf][nf2*2],   a_hi[mf], b0h);
                    mma16816(acc[mf][nf2*2],   a_hi[mf], b0l);
                    mma16816(acc[mf][nf2*2],   a_lo[mf], b0h);
                    mma16816(acc[mf][nf2*2+1], a_hi[mf], b1h);
                    mma16816(acc[mf][nf2*2+1], a_hi[mf], b1l);
                    mma16816(acc[mf][nf2*2+1], a_lo[mf], b1h);
                }
            }
        }
        __syncthreads();
    }

    // ---- epilogue ----
    const int qr = lane >> 2;      // 0..7
    const int qc = lane & 3;

    #pragma unroll
    for (int mf = 0; mf < 2; mf++) {
        const int vox_lo = wm*32 + mf*16 + qr;
        const int vox_hi = vox_lo + 8;
        const long cell_lo = (((long)b*DS + dz)*DS + dy0 + wm)*DS + (vox_lo & 31);
        const long cell_hi = (((long)b*DS + dz)*DS + dy0 + wm)*DS + (vox_hi & 31);
        const float m_lo = m2[cell_lo];
        const float m_hi = m2[cell_hi];
        #pragma unroll
        for (int nf = 0; nf < 8; nf++) {
            const int co = wn*64 + nf*8 + qc*2;
            const float b0 = bias[co], b1 = bias[co + 1];
            acc[mf][nf][0] = (acc[mf][nf][0] + b0) * m_lo;
            acc[mf][nf][1] = (acc[mf][nf][1] + b1) * m_lo;
            acc[mf][nf][2] = (acc[mf][nf][2] + b0) * m_hi;
            acc[mf][nf][3] = (acc[mf][nf][3] + b1) * m_hi;
        }
    }

    if (FUSE_LN) {
        float* ps = s_red;            // [256 vox][2 wn]
        float* qs = s_red + 512;
        __syncthreads();
        #pragma unroll
        for (int mf = 0; mf < 2; mf++) {
            float S_lo = 0.f, Q_lo = 0.f, S_hi = 0.f, Q_hi = 0.f;
            #pragma unroll
            for (int nf = 0; nf < 8; nf++) {
                S_lo += acc[mf][nf][0] + acc[mf][nf][1];
                Q_lo += acc[mf][nf][0]*acc[mf][nf][0] + acc[mf][nf][1]*acc[mf][nf][1];
                S_hi += acc[mf][nf][2] + acc[mf][nf][3];
                Q_hi += acc[mf][nf][2]*acc[mf][nf][2] + acc[mf][nf][3]*acc[mf][nf][3];
            }
            #pragma unroll
            for (int o = 1; o < 4; o <<= 1) {
                S_lo += __shfl_xor_sync(0xffffffffu, S_lo, o);
                Q_lo += __shfl_xor_sync(0xffffffffu, Q_lo, o);
                S_hi += __shfl_xor_sync(0xffffffffu, S_hi, o);
                Q_hi += __shfl_xor_sync(0xffffffffu, Q_hi, o);
            }
            if (qc == 0) {
                const int vox_lo = wm*32 + mf*16 + qr;
                ps[vox_lo*2 + wn] = S_lo;  qs[vox_lo*2 + wn] = Q_lo;
                ps[(vox_lo + 8)*2 + wn] = S_hi;  qs[(vox_lo + 8)*2 + wn] = Q_hi;
            }
        }
        __syncthreads();
        #pragma unroll
        for (int mf = 0; mf < 2; mf++) {
            #pragma unroll
            for (int half = 0; half < 2; half++) {
                const int vox = wm*32 + mf*16 + qr + half*8;
                const long cell = (((long)b*DS + dz)*DS + dy0 + wm)*DS + (vox & 31);
                const float m = m2[cell];
                const float S = ps[vox*2] + ps[vox*2 + 1];
                const float Q = qs[vox*2] + qs[vox*2 + 1];
                const float mu  = S * (1.f/128.f);
                const float var = Q * (1.f/128.f) - mu*mu;
                const float rsv = rsqrtf(var + 1e-6f);
                #pragma unroll
                for (int nf = 0; nf < 8; nf++) {
                    const int co = wn*64 + nf*8 + qc*2;
                    __nv_bfloat162 vh, vl;
                    #pragma unroll
                    for (int e = 0; e < 2; e++) {
                        const float lnv = (acc[mf][nf][half*2 + e] - mu) * rsv;
                        const float sil = (lnv / (1.f + __expf(-lnv))) * m;
                        const __nv_bfloat16 hi = __float2bfloat16(sil);
                        const __nv_bfloat16 lo = __float2bfloat16(sil - __bfloat162float(hi));
                        if (e == 0) { vh.x = hi; vl.x = lo; } else { vh.y = hi; vl.y = lo; }
                    }
                    *(__nv_bfloat162*)(outhi + cell*C2 + co) = vh;
                    *(__nv_bfloat162*)(outlo + cell*C2 + co) = vl;
                }
            }
        }
    } else {
        #pragma unroll
        for (int mf = 0; mf < 2; mf++) {
            #pragma unroll
            for (int half = 0; half < 2; half++) {
                const int vox = wm*32 + mf*16 + qr + half*8;
                const long cell = (((long)b*DS + dz)*DS + dy0 + wm)*DS + (vox & 31);
                #pragma unroll
                for (int nf = 0; nf < 8; nf++) {
                    const int co = wn*64 + nf*8 + qc*2;
                    float2 v;
                    v.x = acc[mf][nf][half*2];
                    v.y = acc[mf][nf][half*2 + 1];
                    *(float2*)(outf + cell*C2 + co) = v;
                }
            }
        }
    }
}

// ---------------- skip linear (64->128) + bias + mask, fused add -------------
__global__ void __launch_bounds__(128)
k_skip(const float* __restrict__ xds, const float* __restrict__ wsk,
       const float* __restrict__ bsk, const float* __restrict__ m2,
       float* __restrict__ out)
{
    __shared__ float s_w[C1*C2];
    __shared__ float s_x[32*C1];

    const int co = threadIdx.x;
    const int dy = blockIdx.x, dz = blockIdx.y, b = blockIdx.z;
    const long cellbase = (((long)b*DS + dz)*DS + dy)*DS;

    {
        const float4* ws = (const float4*)wsk;
        float4* wd = (float4*)s_w;
        #pragma unroll 4
        for (int i = co; i < C1*C2/4; i += 128) wd[i] = ws[i];
        const float4* xs = (const float4*)(xds + cellbase*C1);
        float4* xd = (float4*)s_x;
        #pragma unroll
        for (int i = co; i < 32*C1/4; i += 128) xd[i] = xs[i];
    }
    __syncthreads();

    float acc[32];
    #pragma unroll
    for (int ww = 0; ww < 32; ww++) acc[ww] = 0.f;
    #pragma unroll 2
    for (int ci = 0; ci < C1; ci++) {
        const float wv = s_w[ci*C2 + co];
        #pragma unroll
        for (int ww = 0; ww < 32; ww++)
            acc[ww] += s_x[ww*C1 + ci] * wv;
    }

    const float bvv = bsk[co];
    #pragma unroll 4
    for (int ww = 0; ww < 32; ww++) {
        const float m = m2[cellbase + ww];
        const long i = (cellbase + ww)*C2 + co;
        out[i] = (m != 0.f) ? (out[i] + acc[ww] + bvv) : 0.f;
    }
}

// ---------------- launch ------------------------------------------------------
extern "C" void kernel_launch(void* const* d_in, const int* in_sizes, int n_in,
                              void* d_out, int out_size)
{
    const float* feats = (const float*)d_in[0];
    const void*  mask  = d_in[1];
    const float* gamma1= (const float*)d_in[2];
    const float* beta1 = (const float*)d_in[3];
    const float* w1    = (const float*)d_in[4];
    const float* b1    = (const float*)d_in[5];
    const float* w2    = (const float*)d_in[6];
    const float* b2    = (const float*)d_in[7];
    const float* wsk   = (const float*)d_in[8];
    const float* bsk   = (const float*)d_in[9];
    float* out = (float*)d_out;

    float *p_xds, *p_m2;
    __nv_bfloat16 *p_h1hi, *p_h1lo, *p_c1hi, *p_c1lo;
    unsigned char *p_wA1, *p_wA2;
    cudaGetSymbolAddress((void**)&p_xds,  g_xds);
    cudaGetSymbolAddress((void**)&p_m2,   g_m2);
    cudaGetSymbolAddress((void**)&p_h1hi, g_h1hi);
    cudaGetSymbolAddress((void**)&p_h1lo, g_h1lo);
    cudaGetSymbolAddress((void**)&p_c1hi, g_c1hi);
    cudaGetSymbolAddress((void**)&p_c1lo, g_c1lo);
    cudaGetSymbolAddress((void**)&p_wA1,  g_wA1);
    cudaGetSymbolAddress((void**)&p_wA2,  g_wA2);

    k_detect<<<1, 32>>>((const unsigned int*)mask, in_sizes[1] / 4);
    k_prep_w<<<432, 512>>>(w1, p_wA1, C1);
    k_prep_w<<<864, 512>>>(w2, p_wA2, C2);
    k_ln_ds<<<NCELL, 256>>>(feats, mask, gamma1, beta1);

    const size_t SMEMSZ = 1024 + 2*98304;             // align pad + 2 stage buffers
    dim3 gC(DS/8, DS, NB);                             // (dy strip, dz, b) = (4,32,4)

    cudaFuncSetAttribute(k_convmma<C1, true>,
                         cudaFuncAttributeMaxDynamicSharedMemorySize, (int)SMEMSZ);
    k_convmma<C1, true><<<gC, 512, SMEMSZ>>>(p_h1hi, p_h1lo, p_wA1, b1, p_m2,
                                             nullptr, p_c1hi, p_c1lo);

    cudaFuncSetAttribute(k_convmma<C2, false>,
                         cudaFuncAttributeMaxDynamicSharedMemorySize, (int)SMEMSZ);
    k_convmma<C2, false><<<gC, 512, SMEMSZ>>>(p_c1hi, p_c1lo, p_wA2, b2, p_m2,
                                              out, nullptr, nullptr);

    dim3 gS(DS, DS, NB);
    k_skip<<<gS, 128>>>(p_xds, wsk, bsk, p_m2, out);
}

// round 11
// speedup vs baseline: 1.1306x; 1.1306x over previous
#include <cuda_runtime.h>
#include <cuda_bf16.h>
#include <cstdint>

#define NB 4
#define D0 64
#define C1 64
#define C2 128
#define DS 32
#define NCELL (NB*DS*DS*DS)   // 131072

// ---------------- scratch (device globals) ----------------------------------
__device__ float          g_m2  [NCELL];
__device__ __nv_bfloat16  g_h1hi[NCELL*C1];     // conv1 input hi
__device__ __nv_bfloat16  g_h1lo[NCELL*C1];     // conv1 input lo
__device__ __nv_bfloat16  g_xhi [NCELL*C1];     // skip input hi
__device__ __nv_bfloat16  g_xlo [NCELL*C1];     // skip input lo
__device__ __nv_bfloat16  g_c1hi[NCELL*C2];     // conv2 input hi
__device__ __nv_bfloat16  g_c1lo[NCELL*C2];     // conv2 input lo
__device__ unsigned char  g_wA1[27*1*32768];    // conv1 B tiles (hi+lo)
__device__ unsigned char  g_wA2[(27*2+1)*32768];// conv2 B tiles + skip tile (stage 54)
__device__ int            g_mask_mode;

// ---------------- helpers ----------------------------------------------------
__device__ __forceinline__ uint32_t smem_u32(const void* p){
    uint32_t a;
    asm("{ .reg .u64 t; cvta.to.shared.u64 t, %1; cvt.u32.u64 %0, t; }" : "=r"(a) : "l"(p));
    return a;
}
__device__ __forceinline__ void cpa16z(uint32_t dst, const void* src, bool ok){
    int sz = ok ? 16 : 0;
    asm volatile("cp.async.cg.shared.global [%0], [%1], 16, %2;" :: "r"(dst), "l"(src), "r"(sz));
}
__device__ __forceinline__ void cpa_commit(){ asm volatile("cp.async.commit_group;"); }

__device__ __forceinline__ void ldsm4(uint32_t* r, uint32_t addr){
    asm volatile("ldmatrix.sync.aligned.m8n8.x4.shared.b16 {%0,%1,%2,%3}, [%4];"
        : "=r"(r[0]), "=r"(r[1]), "=r"(r[2]), "=r"(r[3]) : "r"(addr));
}
__device__ __forceinline__ void mma16816(float* d, const uint32_t* a, const uint32_t* b){
    asm volatile("mma.sync.aligned.m16n8k16.row.col.f32.bf16.bf16.f32 "
        "{%0,%1,%2,%3}, {%4,%5,%6,%7}, {%8,%9}, {%0,%1,%2,%3};"
        : "+f"(d[0]), "+f"(d[1]), "+f"(d[2]), "+f"(d[3])
        : "r"(a[0]), "r"(a[1]), "r"(a[2]), "r"(a[3]), "r"(b[0]), "r"(b[1]));
}
__device__ __host__ __forceinline__ uint32_t swz(uint32_t row, uint32_t bytecol){
    uint32_t off = row*128u + bytecol;
    return off ^ ((off >> 3) & 0x70u);
}

// ---------------- mask dtype detection ---------------------------------------
__global__ void k_detect(const unsigned int* __restrict__ m, int nwords)
{
    if (threadIdx.x == 0 && blockIdx.x == 0) {
        int mode = 0;
        for (int i = 0; i < nwords; i++) {
            unsigned w = m[i];
            if (w == 0u) continue;
            if (w == 1u)               mode = 0;
            else if (w == 0x3F800000u) mode = 0;
            else                       mode = 2;
            break;
        }
        g_mask_mode = mode;
    }
}
__device__ __forceinline__ bool mask_at(const void* m, long v, int mode)
{
    if (mode == 2) return ((const unsigned char*)m)[v] != 0;
    return ((const unsigned int*)m)[v] != 0u;
}

// ---------------- weight prep: transpose + hi/lo split + smem layout ---------
__global__ void k_prep_w(const float* __restrict__ w, unsigned char* __restrict__ dst, int CIN)
{
    const int total = 27*CIN*128;
    for (int e = blockIdx.x*blockDim.x + threadIdx.x; e < total; e += gridDim.x*blockDim.x) {
        const int t   = e / (CIN*128);
        const int rem = e - t*(CIN*128);
        const int ci  = rem >> 7;
        const int co  = rem & 127;
        const float wv = w[e];
        const __nv_bfloat16 hi = __float2bfloat16(wv);
        const __nv_bfloat16 lo = __float2bfloat16(wv - __bfloat162float(hi));
        const int kc = ci >> 6, cil = ci & 63;
        const int stage = t*(CIN >> 6) + kc;
        const uint32_t off = swz((uint32_t)co, (uint32_t)cil*2u);
        unsigned char* base = dst + (long)stage*32768;
        *(__nv_bfloat16*)(base + off)         = hi;
        *(__nv_bfloat16*)(base + 16384 + off) = lo;
    }
}

// skip weight: wsk [64 ci][128 co] -> stage-54 tile of g_wA2
__global__ void k_prep_skipw(const float* __restrict__ wsk, unsigned char* __restrict__ dst)
{
    const int e = blockIdx.x*blockDim.x + threadIdx.x;
    if (e < 64*128) {
        const int ci = e >> 7;
        const int co = e & 127;
        const float wv = wsk[e];
        const __nv_bfloat16 hi = __float2bfloat16(wv);
        const __nv_bfloat16 lo = __float2bfloat16(wv - __bfloat162float(hi));
        const uint32_t off = swz((uint32_t)co, (uint32_t)ci*2u);
        *(__nv_bfloat16*)(dst + off)         = hi;
        *(__nv_bfloat16*)(dst + 16384 + off) = lo;
    }
}

// ---------------- K1: LN1+affine+SiLU+mask + 2x downsample -------------------
__global__ void __launch_bounds__(256)
k_ln_ds(const float* __restrict__ feats, const void* __restrict__ mask,
        const float* __restrict__ gamma, const float* __restrict__ beta)
{
    const int bid = blockIdx.x;
    const int dx = bid & 31, dy = (bid >> 5) & 31, dz = (bid >> 10) & 31, b = bid >> 15;
    const int tid = threadIdx.x;
    const int s   = tid >> 5;
    const int ln  = tid & 31;
    const int mode = g_mask_mode;

    __shared__ float sh_h[8*64];
    __shared__ float sh_x[8*64];
    __shared__ int   sh_c[8];

    const int z = 2*dz + (s >> 2);
    const int y = 2*dy + ((s >> 1) & 1);
    const int x = 2*dx + (s & 1);
    const long v = (((long)b*D0 + z)*D0 + y)*D0 + x;
    const bool act = mask_at(mask, v, mode);

    const float2 xv = *(const float2*)(feats + v*C1 + ln*2);
    float a = xv.x + xv.y;
    float q = xv.x*xv.x + xv.y*xv.y;
    #pragma unroll
    for (int o = 16; o > 0; o >>= 1) {
        a += __shfl_xor_sync(0xffffffffu, a, o);
        q += __shfl_xor_sync(0xffffffffu, q, o);
    }
    const float mu  = a * (1.f/64.f);
    const float var = q * (1.f/64.f) - mu*mu;
    const float rs  = rsqrtf(var + 1e-6f);

    const float2 g  = *(const float2*)(gamma + ln*2);
    const float2 be = *(const float2*)(beta  + ln*2);
    float h0 = (xv.x - mu)*rs*g.x + be.x;
    float h1 = (xv.y - mu)*rs*g.y + be.y;
    h0 = h0 / (1.f + __expf(-h0));
    h1 = h1 / (1.f + __expf(-h1));

    sh_h[s*64 + ln*2    ] = act ? h0 : 0.f;
    sh_h[s*64 + ln*2 + 1] = act ? h1 : 0.f;
    sh_x[s*64 + ln*2    ] = act ? xv.x : 0.f;
    sh_x[s*64 + ln*2 + 1] = act ? xv.y : 0.f;
    if (ln == 0) sh_c[s] = act ? 1 : 0;
    __syncthreads();

    if (tid < 64) {
        float hs = 0.f, xs = 0.f;
        int cnt = 0;
        #pragma unroll
        for (int k = 0; k < 8; k++) {
            hs += sh_h[k*64 + tid];
            xs += sh_x[k*64 + tid];
            cnt += sh_c[k];
        }
        const float inv = 1.f / (float)max(cnt, 1);
        const float hv = hs * inv;
        const float xm = xs * inv;
        const __nv_bfloat16 hhi = __float2bfloat16(hv);
        const __nv_bfloat16 hlo = __float2bfloat16(hv - __bfloat162float(hhi));
        const __nv_bfloat16 xhi = __float2bfloat16(xm);
        const __nv_bfloat16 xlo = __float2bfloat16(xm - __bfloat162float(xhi));
        g_h1hi[(long)bid*C1 + tid] = hhi;
        g_h1lo[(long)bid*C1 + tid] = hlo;
        g_xhi [(long)bid*C1 + tid] = xhi;
        g_xlo [(long)bid*C1 + tid] = xlo;
        if (tid == 0) g_m2[bid] = (cnt > 0) ? 1.f : 0.f;
    }
}

// ---------------- conv via mma.sync (split-bf16 3-term) ----------------------
// Block 256 thr / 8 warps. Tile: 128 voxels (4 dy rows x 32 x) x 128 cout.
// Triple-buffered stages; conv2 appends skip GEMM as final stage (HAS_SKIP).
template<int CIN, bool FUSE_LN, bool HAS_SKIP>
__global__ void __launch_bounds__(256, 1)
k_convmma(const __nv_bfloat16* __restrict__ inhi, const __nv_bfloat16* __restrict__ inlo,
          const __nv_bfloat16* __restrict__ skhi, const __nv_bfloat16* __restrict__ sklo,
          const unsigned char* __restrict__ wA, const float* __restrict__ bias,
          const float* __restrict__ bias2, const float* __restrict__ m2,
          float* __restrict__ outf,
          __nv_bfloat16* __restrict__ outhi, __nv_bfloat16* __restrict__ outlo)
{
    constexpr int NKC = CIN / 64;
    constexpr int NS  = 27 * NKC;
    constexpr int NST = NS + (HAS_SKIP ? 1 : 0);

    extern __shared__ char smraw[];
    const uint32_t sb0 = smem_u32(smraw);
    const uint32_t BUF = (sb0 + 1023) & ~1023u;
    float* s_red = (float*)(smraw + (BUF - sb0));

    const int tid  = threadIdx.x;
    const int lane = tid & 31;
    const int w    = tid >> 5;
    const int wm   = w >> 1;          // 0..3
    const int wn   = w & 1;           // 0..1
    const int dy0  = blockIdx.x * 4;
    const int dz   = blockIdx.y;
    const int b    = blockIdx.z;

    float acc[2][8][4];
    #pragma unroll
    for (int mf = 0; mf < 2; mf++)
        #pragma unroll
        for (int nf = 0; nf < 8; nf++)
            #pragma unroll
            for (int k = 0; k < 4; k++) acc[mf][nf][k] = 0.f;

    // ---- stage copier ----
    auto stage_copy = [&](int s, int p){
        const uint32_t base = BUF + (uint32_t)p * 65536u;
        if (HAS_SKIP && s == NS) {
            // skip stage: A from xds (64 ci, no spatial shift), B = stage-54 tile
            #pragma unroll
            for (int i = 0; i < 16; i++) {
                const int flat = tid + i*256;
                if (flat < 2048) {
                    const int half = flat >> 10;
                    const int f    = flat & 1023;
                    const int vox  = f >> 3;
                    const int seg  = f & 7;
                    const long cell = (((long)b*DS + dz)*DS + dy0 + (vox >> 5))*DS + (vox & 31);
                    const __nv_bfloat16* src =
                        (half ? sklo : skhi) + cell*C1 + seg*8;
                    cpa16z(base + (uint32_t)half*16384u + swz((uint32_t)vox, (uint32_t)seg*16u),
                           src, true);
                } else {
                    const int f = flat - 2048;
                    cpa16z(base + 32768u + (uint32_t)f*16u,
                           wA + (long)s*32768 + (long)f*16, true);
                }
            }
            cpa_commit();
            return;
        }
        const int t  = s / NKC;
        const int kc = s - t*NKC;
        const int kd = t / 9;
        const int r9 = t - kd*9;
        const int kh = r9 / 3;
        const int kw = r9 - kh*3;
        const int z  = dz + kd - 1;
        const bool zok = (unsigned)z < DS;
        #pragma unroll
        for (int i = 0; i < 16; i++) {
            const int flat = tid + i*256;            // 0..4095 (16B units)
            if (flat < 2048) {                       // A input tiles (hi, lo)
                const int half = flat >> 10;
                const int f    = flat & 1023;
                const int vox  = f >> 3;
                const int seg  = f & 7;
                const int r    = vox >> 5;
                const int x    = vox & 31;
                const int y    = dy0 + r + kh - 1;
                const int xx   = x + kw - 1;
                const bool ok  = zok && ((unsigned)y < DS) && ((unsigned)xx < DS);
                const long cell = ok ? ((((long)b*DS + z)*DS + y)*DS + xx) : 0;
                const __nv_bfloat16* src =
                    (half ? inlo : inhi) + cell*CIN + kc*64 + seg*8;
                cpa16z(base + (uint32_t)half*16384u + swz((uint32_t)vox, (uint32_t)seg*16u),
                       src, ok);
            } else {                                  // B weight tiles
                const int f = flat - 2048;
                cpa16z(base + 32768u + (uint32_t)f*16u,
                       wA + (long)s*32768 + (long)f*16, true);
            }
        }
        cpa_commit();
    };

    stage_copy(0, 0);
    if (NST > 1) stage_copy(1, 1);

    int p = 0;   // buffer index of stage s (s % 3 tracked incrementally)
    for (int s = 0; s < NST; s++) {
        if (s + 2 < NST) {
            int p2 = p + 2; if (p2 >= 3) p2 -= 3;
            stage_copy(s + 2, p2);
        }
        const int ahead = (NST - 1 < s + 2 ? NST - 1 : s + 2) - s;
        if (ahead == 2)      asm volatile("cp.async.wait_group 2;");
        else if (ahead == 1) asm volatile("cp.async.wait_group 1;");
        else                 asm volatile("cp.async.wait_group 0;");
        __syncthreads();

        const uint32_t Ab = BUF + (uint32_t)p*65536u;
        const uint32_t Bb = Ab + 32768u;

        #pragma unroll
        for (int ks = 0; ks < 4; ks++) {
            const uint32_t colb = (uint32_t)(ks*16 + ((lane >> 4) & 1)*8) * 2u;
            uint32_t a_hi[2][4], a_lo[2][4];
            #pragma unroll
            for (int mf = 0; mf < 2; mf++) {
                const uint32_t row = (uint32_t)(wm*32 + mf*16 + (lane & 15));
                const uint32_t ad = Ab + swz(row, colb);
                ldsm4(a_hi[mf], ad);
                ldsm4(a_lo[mf], ad + 16384u);
            }
            uint32_t b_hi[8][2], b_lo[8][2];
            #pragma unroll
            for (int nf2 = 0; nf2 < 4; nf2++) {
                const uint32_t row = (uint32_t)(wn*64 + nf2*16 + (lane & 15));
                const uint32_t ad = Bb + swz(row, colb);
                uint32_t r4[4];
                ldsm4(r4, ad);
                b_hi[nf2*2][0] = r4[0]; b_hi[nf2*2+1][0] = r4[1];
                b_hi[nf2*2][1] = r4[2]; b_hi[nf2*2+1][1] = r4[3];
                ldsm4(r4, ad + 16384u);
                b_lo[nf2*2][0] = r4[0]; b_lo[nf2*2+1][0] = r4[1];
                b_lo[nf2*2][1] = r4[2]; b_lo[nf2*2+1][1] = r4[3];
            }
            #pragma unroll
            for (int mf = 0; mf < 2; mf++)
                #pragma unroll
                for (int nf = 0; nf < 8; nf++) {
                    mma16816(acc[mf][nf], a_hi[mf], b_hi[nf]);
                    mma16816(acc[mf][nf], a_hi[mf], b_lo[nf]);
                    mma16816(acc[mf][nf], a_lo[mf], b_hi[nf]);
                }
        }
        __syncthreads();
        p++; if (p == 3) p = 0;
    }

    // ---- epilogue ----
    const int qr = lane >> 2;
    const int qc = lane & 3;

    #pragma unroll
    for (int mf = 0; mf < 2; mf++) {
        const int vox_lo = wm*32 + mf*16 + qr;
        const int vox_hi = vox_lo + 8;
        const long cell_lo = (((long)b*DS + dz)*DS + dy0 + (vox_lo >> 5))*DS + (vox_lo & 31);
        const long cell_hi = (((long)b*DS + dz)*DS + dy0 + (vox_hi >> 5))*DS + (vox_hi & 31);
        const float m_lo = m2[cell_lo];
        const float m_hi = m2[cell_hi];
        #pragma unroll
        for (int nf = 0; nf < 8; nf++) {
            const int co = wn*64 + nf*8 + qc*2;
            float b0 = bias[co], b1 = bias[co + 1];
            if (HAS_SKIP) { b0 += bias2[co]; b1 += bias2[co + 1]; }
            acc[mf][nf][0] = (acc[mf][nf][0] + b0) * m_lo;
            acc[mf][nf][1] = (acc[mf][nf][1] + b1) * m_lo;
            acc[mf][nf][2] = (acc[mf][nf][2] + b0) * m_hi;
            acc[mf][nf][3] = (acc[mf][nf][3] + b1) * m_hi;
        }
    }

    if (FUSE_LN) {
        float* ps = s_red;            // [128 vox][2 wn]
        float* qs = s_red + 256;
        __syncthreads();
        #pragma unroll
        for (int mf = 0; mf < 2; mf++) {
            float S_lo = 0.f, Q_lo = 0.f, S_hi = 0.f, Q_hi = 0.f;
            #pragma unroll
            for (int nf = 0; nf < 8; nf++) {
                S_lo += acc[mf][nf][0] + acc[mf][nf][1];
                Q_lo += acc[mf][nf][0]*acc[mf][nf][0] + acc[mf][nf][1]*acc[mf][nf][1];
                S_hi += acc[mf][nf][2] + acc[mf][nf][3];
                Q_hi += acc[mf][nf][2]*acc[mf][nf][2] + acc[mf][nf][3]*acc[mf][nf][3];
            }
            #pragma unroll
            for (int o = 1; o < 4; o <<= 1) {
                S_lo += __shfl_xor_sync(0xffffffffu, S_lo, o);
                Q_lo += __shfl_xor_sync(0xffffffffu, Q_lo, o);
                S_hi += __shfl_xor_sync(0xffffffffu, S_hi, o);
                Q_hi += __shfl_xor_sync(0xffffffffu, Q_hi, o);
            }
            if (qc == 0) {
                const int vox_lo = wm*32 + mf*16 + qr;
                ps[vox_lo*2 + wn] = S_lo;  qs[vox_lo*2 + wn] = Q_lo;
                ps[(vox_lo + 8)*2 + wn] = S_hi;  qs[(vox_lo + 8)*2 + wn] = Q_hi;
            }
        }
        __syncthreads();
        #pragma unroll
        for (int mf = 0; mf < 2; mf++) {
            #pragma unroll
            for (int half = 0; half < 2; half++) {
                const int vox = wm*32 + mf*16 + qr + half*8;
                const long cell = (((long)b*DS + dz)*DS + dy0 + (vox >> 5))*DS + (vox & 31);
                const float m = m2[cell];
                const float S = ps[vox*2] + ps[vox*2 + 1];
                const float Q = qs[vox*2] + qs[vox*2 + 1];
                const float mu  = S * (1.f/128.f);
                const float var = Q * (1.f/128.f) - mu*mu;
                const float rsv = rsqrtf(var + 1e-6f);
                #pragma unroll
                for (int nf = 0; nf < 8; nf++) {
                    const int co = wn*64 + nf*8 + qc*2;
                    __nv_bfloat162 vh, vl;
                    #pragma unroll
                    for (int e = 0; e < 2; e++) {
                        const float lnv = (acc[mf][nf][half*2 + e] - mu) * rsv;
                        const float sil = (lnv / (1.f + __expf(-lnv))) * m;
                        const __nv_bfloat16 hi = __float2bfloat16(sil);
                        const __nv_bfloat16 lo = __float2bfloat16(sil - __bfloat162float(hi));
                        if (e == 0) { vh.x = hi; vl.x = lo; } else { vh.y = hi; vl.y = lo; }
                    }
                    *(__nv_bfloat162*)(outhi + cell*C2 + co) = vh;
                    *(__nv_bfloat162*)(outlo + cell*C2 + co) = vl;
                }
            }
        }
    } else {
        #pragma unroll
        for (int mf = 0; mf < 2; mf++) {
            #pragma unroll
            for (int half = 0; half < 2; half++) {
                const int vox = wm*32 + mf*16 + qr + half*8;
                const long cell = (((long)b*DS + dz)*DS + dy0 + (vox >> 5))*DS + (vox & 31);
                #pragma unroll
                for (int nf = 0; nf < 8; nf++) {
                    const int co = wn*64 + nf*8 + qc*2;
                    float2 v;
                    v.x = acc[mf][nf][half*2];
                    v.y = acc[mf][nf][half*2 + 1];
                    *(float2*)(outf + cell*C2 + co) = v;
                }
            }
        }
    }
}

// ---------------- launch ------------------------------------------------------
extern "C" void kernel_launch(void* const* d_in, const int* in_sizes, int n_in,
                              void* d_out, int out_size)
{
    const float* feats = (const float*)d_in[0];
    const void*  mask  = d_in[1];
    const float* gamma1= (const float*)d_in[2];
    const float* beta1 = (const float*)d_in[3];
    const float* w1    = (const float*)d_in[4];
    const float* b1    = (const float*)d_in[5];
    const float* w2    = (const float*)d_in[6];
    const float* b2    = (const float*)d_in[7];
    const float* wsk   = (const float*)d_in[8];
    const float* bsk   = (const float*)d_in[9];
    float* out = (float*)d_out;

    float *p_m2;
    __nv_bfloat16 *p_h1hi, *p_h1lo, *p_xhi, *p_xlo, *p_c1hi, *p_c1lo;
    unsigned char *p_wA1, *p_wA2;
    cudaGetSymbolAddress((void**)&p_m2,   g_m2);
    cudaGetSymbolAddress((void**)&p_h1hi, g_h1hi);
    cudaGetSymbolAddress((void**)&p_h1lo, g_h1lo);
    cudaGetSymbolAddress((void**)&p_xhi,  g_xhi);
    cudaGetSymbolAddress((void**)&p_xlo,  g_xlo);
    cudaGetSymbolAddress((void**)&p_c1hi, g_c1hi);
    cudaGetSymbolAddress((void**)&p_c1lo, g_c1lo);
    cudaGetSymbolAddress((void**)&p_wA1,  g_wA1);
    cudaGetSymbolAddress((void**)&p_wA2,  g_wA2);

    k_detect<<<1, 32>>>((const unsigned int*)mask, in_sizes[1] / 4);
    k_prep_w<<<432, 512>>>(w1, p_wA1, C1);
    k_prep_w<<<864, 512>>>(w2, p_wA2, C2);
    k_prep_skipw<<<16, 512>>>(wsk, p_wA2 + (long)54*32768);
    k_ln_ds<<<NCELL, 256>>>(feats, mask, gamma1, beta1);

    const size_t SMEMSZ = 1024 + 3*65536;             // align pad + 3 stage buffers
    dim3 gC(DS/4, DS, NB);                             // (dy strip, dz, b) = (8,32,4)

    cudaFuncSetAttribute(k_convmma<C1, true, false>,
                         cudaFuncAttributeMaxDynamicSharedMemorySize, (int)SMEMSZ);
    k_convmma<C1, true, false><<<gC, 256, SMEMSZ>>>(p_h1hi, p_h1lo, nullptr, nullptr,
                                                    p_wA1, b1, nullptr, p_m2,
                                                    nullptr, p_c1hi, p_c1lo);

    cudaFuncSetAttribute(k_convmma<C2, false, true>,
                         cudaFuncAttributeMaxDynamicSharedMemorySize, (int)SMEMSZ);
    k_convmma<C2, false, true><<<gC, 256, SMEMSZ>>>(p_c1hi, p_c1lo, p_xhi, p_xlo,
                                                    p_wA2, b2, bsk, p_m2,
                                                    out, nullptr, nullptr);
}

// round 12
// speedup vs baseline: 1.1609x; 1.0268x over previous
#include <cuda_runtime.h>
#include <cuda_bf16.h>
#include <cstdint>

#define NB 4
#define D0 64
#define C1 64
#define C2 128
#define DS 32
#define NCELL (NB*DS*DS*DS)   // 131072

// ---------------- scratch (device globals) ----------------------------------
__device__ float          g_m2  [NCELL];
__device__ __nv_bfloat16  g_h1hi[NCELL*C1];     // conv1 input hi
__device__ __nv_bfloat16  g_h1lo[NCELL*C1];     // conv1 input lo
__device__ __nv_bfloat16  g_xhi [NCELL*C1];     // skip input hi
__device__ __nv_bfloat16  g_xlo [NCELL*C1];     // skip input lo
__device__ __nv_bfloat16  g_c1hi[NCELL*C2];     // conv2 input hi
__device__ __nv_bfloat16  g_c1lo[NCELL*C2];     // conv2 input lo
__device__ unsigned char  g_wA1[27*1*32768];    // conv1 B tiles (hi+lo)
__device__ unsigned char  g_wA2[(27*2+1)*32768];// conv2 B tiles + skip tile (stage 54)
__device__ int            g_mask_mode;

// ---------------- helpers ----------------------------------------------------
__device__ __forceinline__ uint32_t smem_u32(const void* p){
    uint32_t a;
    asm("{ .reg .u64 t; cvta.to.shared.u64 t, %1; cvt.u32.u64 %0, t; }" : "=r"(a) : "l"(p));
    return a;
}
__device__ __forceinline__ void cpa16z(uint32_t dst, const void* src, bool ok){
    int sz = ok ? 16 : 0;
    asm volatile("cp.async.cg.shared.global [%0], [%1], 16, %2;" :: "r"(dst), "l"(src), "r"(sz));
}
__device__ __forceinline__ void cpa_commit(){ asm volatile("cp.async.commit_group;"); }

__device__ __forceinline__ void ldsm4(uint32_t* r, uint32_t addr){
    asm volatile("ldmatrix.sync.aligned.m8n8.x4.shared.b16 {%0,%1,%2,%3}, [%4];"
        : "=r"(r[0]), "=r"(r[1]), "=r"(r[2]), "=r"(r[3]) : "r"(addr));
}
__device__ __forceinline__ void mma16816(float* d, const uint32_t* a, const uint32_t* b){
    asm volatile("mma.sync.aligned.m16n8k16.row.col.f32.bf16.bf16.f32 "
        "{%0,%1,%2,%3}, {%4,%5,%6,%7}, {%8,%9}, {%0,%1,%2,%3};"
        : "+f"(d[0]), "+f"(d[1]), "+f"(d[2]), "+f"(d[3])
        : "r"(a[0]), "r"(a[1]), "r"(a[2]), "r"(a[3]), "r"(b[0]), "r"(b[1]));
}
__device__ __host__ __forceinline__ uint32_t swz(uint32_t row, uint32_t bytecol){
    uint32_t off = row*128u + bytecol;
    return off ^ ((off >> 3) & 0x70u);
}

// ---------------- mask dtype detection ---------------------------------------
__global__ void k_detect(const unsigned int* __restrict__ m, int nwords)
{
    if (threadIdx.x == 0 && blockIdx.x == 0) {
        int mode = 0;
        for (int i = 0; i < nwords; i++) {
            unsigned w = m[i];
            if (w == 0u) continue;
            if (w == 1u)               mode = 0;
            else if (w == 0x3F800000u) mode = 0;
            else                       mode = 2;
            break;
        }
        g_mask_mode = mode;
    }
}
__device__ __forceinline__ bool mask_at(const void* m, long v, int mode)
{
    if (mode == 2) return ((const unsigned char*)m)[v] != 0;
    return ((const unsigned int*)m)[v] != 0u;
}

// ---------------- weight prep: transpose + hi/lo split + smem layout ---------
__global__ void k_prep_w(const float* __restrict__ w, unsigned char* __restrict__ dst, int CIN)
{
    const int total = 27*CIN*128;
    for (int e = blockIdx.x*blockDim.x + threadIdx.x; e < total; e += gridDim.x*blockDim.x) {
        const int t   = e / (CIN*128);
        const int rem = e - t*(CIN*128);
        const int ci  = rem >> 7;
        const int co  = rem & 127;
        const float wv = w[e];
        const __nv_bfloat16 hi = __float2bfloat16(wv);
        const __nv_bfloat16 lo = __float2bfloat16(wv - __bfloat162float(hi));
        const int kc = ci >> 6, cil = ci & 63;
        const int stage = t*(CIN >> 6) + kc;
        const uint32_t off = swz((uint32_t)co, (uint32_t)cil*2u);
        unsigned char* base = dst + (long)stage*32768;
        *(__nv_bfloat16*)(base + off)         = hi;
        *(__nv_bfloat16*)(base + 16384 + off) = lo;
    }
}

// skip weight: wsk [64 ci][128 co] -> stage-54 tile of g_wA2
__global__ void k_prep_skipw(const float* __restrict__ wsk, unsigned char* __restrict__ dst)
{
    const int e = blockIdx.x*blockDim.x + threadIdx.x;
    if (e < 64*128) {
        const int ci = e >> 7;
        const int co = e & 127;
        const float wv = wsk[e];
        const __nv_bfloat16 hi = __float2bfloat16(wv);
        const __nv_bfloat16 lo = __float2bfloat16(wv - __bfloat162float(hi));
        const uint32_t off = swz((uint32_t)co, (uint32_t)ci*2u);
        *(__nv_bfloat16*)(dst + off)         = hi;
        *(__nv_bfloat16*)(dst + 16384 + off) = lo;
    }
}

// ---------------- K1: LN1+affine+SiLU+mask + 2x downsample -------------------
__global__ void __launch_bounds__(256)
k_ln_ds(const float* __restrict__ feats, const void* __restrict__ mask,
        const float* __restrict__ gamma, const float* __restrict__ beta)
{
    const int bid = blockIdx.x;
    const int dx = bid & 31, dy = (bid >> 5) & 31, dz = (bid >> 10) & 31, b = bid >> 15;
    const int tid = threadIdx.x;
    const int s   = tid >> 5;
    const int ln  = tid & 31;
    const int mode = g_mask_mode;

    __shared__ float sh_h[8*64];
    __shared__ float sh_x[8*64];
    __shared__ int   sh_c[8];

    const int z = 2*dz + (s >> 2);
    const int y = 2*dy + ((s >> 1) & 1);
    const int x = 2*dx + (s & 1);
    const long v = (((long)b*D0 + z)*D0 + y)*D0 + x;
    const bool act = mask_at(mask, v, mode);

    const float2 xv = *(const float2*)(feats + v*C1 + ln*2);
    float a = xv.x + xv.y;
    float q = xv.x*xv.x + xv.y*xv.y;
    #pragma unroll
    for (int o = 16; o > 0; o >>= 1) {
        a += __shfl_xor_sync(0xffffffffu, a, o);
        q += __shfl_xor_sync(0xffffffffu, q, o);
    }
    const float mu  = a * (1.f/64.f);
    const float var = q * (1.f/64.f) - mu*mu;
    const float rs  = rsqrtf(var + 1e-6f);

    const float2 g  = *(const float2*)(gamma + ln*2);
    const float2 be = *(const float2*)(beta  + ln*2);
    float h0 = (xv.x - mu)*rs*g.x + be.x;
    float h1 = (xv.y - mu)*rs*g.y + be.y;
    h0 = h0 / (1.f + __expf(-h0));
    h1 = h1 / (1.f + __expf(-h1));

    sh_h[s*64 + ln*2    ] = act ? h0 : 0.f;
    sh_h[s*64 + ln*2 + 1] = act ? h1 : 0.f;
    sh_x[s*64 + ln*2    ] = act ? xv.x : 0.f;
    sh_x[s*64 + ln*2 + 1] = act ? xv.y : 0.f;
    if (ln == 0) sh_c[s] = act ? 1 : 0;
    __syncthreads();

    if (tid < 64) {
        float hs = 0.f, xs = 0.f;
        int cnt = 0;
        #pragma unroll
        for (int k = 0; k < 8; k++) {
            hs += sh_h[k*64 + tid];
            xs += sh_x[k*64 + tid];
            cnt += sh_c[k];
        }
        const float inv = 1.f / (float)max(cnt, 1);
        const float hv = hs * inv;
        const float xm = xs * inv;
        const __nv_bfloat16 hhi = __float2bfloat16(hv);
        const __nv_bfloat16 hlo = __float2bfloat16(hv - __bfloat162float(hhi));
        const __nv_bfloat16 xhi = __float2bfloat16(xm);
        const __nv_bfloat16 xlo = __float2bfloat16(xm - __bfloat162float(xhi));
        g_h1hi[(long)bid*C1 + tid] = hhi;
        g_h1lo[(long)bid*C1 + tid] = hlo;
        g_xhi [(long)bid*C1 + tid] = xhi;
        g_xlo [(long)bid*C1 + tid] = xlo;
        if (tid == 0) g_m2[bid] = (cnt > 0) ? 1.f : 0.f;
    }
}

// ---------------- conv via mma.sync (split-bf16 3-term) ----------------------
// Block 256 thr / 8 warps. Tile: 128 voxels (4 dy rows x 32 x) x 128 cout.
// Triple-buffered, ONE barrier per stage (prefetch issued post-barrier).
// MMA order is term-major: 3 passes over 16 independent acc fragments.
template<int CIN, bool FUSE_LN, bool HAS_SKIP>
__global__ void __launch_bounds__(256, 1)
k_convmma(const __nv_bfloat16* __restrict__ inhi, const __nv_bfloat16* __restrict__ inlo,
          const __nv_bfloat16* __restrict__ skhi, const __nv_bfloat16* __restrict__ sklo,
          const unsigned char* __restrict__ wA, const float* __restrict__ bias,
          const float* __restrict__ bias2, const float* __restrict__ m2,
          float* __restrict__ outf,
          __nv_bfloat16* __restrict__ outhi, __nv_bfloat16* __restrict__ outlo)
{
    constexpr int NKC = CIN / 64;
    constexpr int NS  = 27 * NKC;
    constexpr int NST = NS + (HAS_SKIP ? 1 : 0);

    extern __shared__ char smraw[];
    const uint32_t sb0 = smem_u32(smraw);
    const uint32_t BUF = (sb0 + 1023) & ~1023u;
    float* s_red = (float*)(smraw + (BUF - sb0));

    const int tid  = threadIdx.x;
    const int lane = tid & 31;
    const int w    = tid >> 5;
    const int wm   = w >> 1;          // 0..3
    const int wn   = w & 1;           // 0..1
    const int dy0  = blockIdx.x * 4;
    const int dz   = blockIdx.y;
    const int b    = blockIdx.z;

    float acc[2][8][4];
    #pragma unroll
    for (int mf = 0; mf < 2; mf++)
        #pragma unroll
        for (int nf = 0; nf < 8; nf++)
            #pragma unroll
            for (int k = 0; k < 4; k++) acc[mf][nf][k] = 0.f;

    // ---- stage copier ----
    auto stage_copy = [&](int s, int p){
        const uint32_t base = BUF + (uint32_t)p * 65536u;
        if (HAS_SKIP && s == NS) {
            #pragma unroll
            for (int i = 0; i < 16; i++) {
                const int flat = tid + i*256;
                if (flat < 2048) {
                    const int half = flat >> 10;
                    const int f    = flat & 1023;
                    const int vox  = f >> 3;
                    const int seg  = f & 7;
                    const long cell = (((long)b*DS + dz)*DS + dy0 + (vox >> 5))*DS + (vox & 31);
                    const __nv_bfloat16* src =
                        (half ? sklo : skhi) + cell*C1 + seg*8;
                    cpa16z(base + (uint32_t)half*16384u + swz((uint32_t)vox, (uint32_t)seg*16u),
                           src, true);
                } else {
                    const int f = flat - 2048;
                    cpa16z(base + 32768u + (uint32_t)f*16u,
                           wA + (long)s*32768 + (long)f*16, true);
                }
            }
            cpa_commit();
            return;
        }
        const int t  = s / NKC;
        const int kc = s - t*NKC;
        const int kd = t / 9;
        const int r9 = t - kd*9;
        const int kh = r9 / 3;
        const int kw = r9 - kh*3;
        const int z  = dz + kd - 1;
        const bool zok = (unsigned)z < DS;
        #pragma unroll
        for (int i = 0; i < 16; i++) {
            const int flat = tid + i*256;            // 0..4095 (16B units)
            if (flat < 2048) {                       // A input tiles (hi, lo)
                const int half = flat >> 10;
                const int f    = flat & 1023;
                const int vox  = f >> 3;
                const int seg  = f & 7;
                const int r    = vox >> 5;
                const int x    = vox & 31;
                const int y    = dy0 + r + kh - 1;
                const int xx   = x + kw - 1;
                const bool ok  = zok && ((unsigned)y < DS) && ((unsigned)xx < DS);
                const long cell = ok ? ((((long)b*DS + z)*DS + y)*DS + xx) : 0;
                const __nv_bfloat16* src =
                    (half ? inlo : inhi) + cell*CIN + kc*64 + seg*8;
                cpa16z(base + (uint32_t)half*16384u + swz((uint32_t)vox, (uint32_t)seg*16u),
                       src, ok);
            } else {                                  // B weight tiles
                const int f = flat - 2048;
                cpa16z(base + 32768u + (uint32_t)f*16u,
                       wA + (long)s*32768 + (long)f*16, true);
            }
        }
        cpa_commit();
    };

    stage_copy(0, 0);
    if (NST > 1) stage_copy(1, 1);

    int p = 0;   // buffer index of stage s
    for (int s = 0; s < NST; s++) {
        // complete stage s's copy (allow s+1 to stay pending)
        if (s < NST - 1) asm volatile("cp.async.wait_group 1;");
        else             asm volatile("cp.async.wait_group 0;");
        __syncthreads();   // all warps finished compute s-1; copies of s visible

        // prefetch s+2 into buffer of s-1 (safe: post-barrier)
        if (s + 2 < NST) {
            int p2 = p + 2; if (p2 >= 3) p2 -= 3;
            stage_copy(s + 2, p2);
        }

        const uint32_t Ab = BUF + (uint32_t)p*65536u;
        const uint32_t Bb = Ab + 32768u;

        #pragma unroll
        for (int ks = 0; ks < 4; ks++) {
            const uint32_t colb = (uint32_t)(ks*16 + ((lane >> 4) & 1)*8) * 2u;
            uint32_t a_hi[2][4], a_lo[2][4];
            #pragma unroll
            for (int mf = 0; mf < 2; mf++) {
                const uint32_t row = (uint32_t)(wm*32 + mf*16 + (lane & 15));
                const uint32_t ad = Ab + swz(row, colb);
                ldsm4(a_hi[mf], ad);
                ldsm4(a_lo[mf], ad + 16384u);
            }
            uint32_t b_hi[8][2], b_lo[8][2];
            #pragma unroll
            for (int nf2 = 0; nf2 < 4; nf2++) {
                const uint32_t row = (uint32_t)(wn*64 + nf2*16 + (lane & 15));
                const uint32_t ad = Bb + swz(row, colb);
                uint32_t r4[4];
                ldsm4(r4, ad);
                b_hi[nf2*2][0] = r4[0]; b_hi[nf2*2+1][0] = r4[1];
                b_hi[nf2*2][1] = r4[2]; b_hi[nf2*2+1][1] = r4[3];
                ldsm4(r4, ad + 16384u);
                b_lo[nf2*2][0] = r4[0]; b_lo[nf2*2+1][0] = r4[1];
                b_lo[nf2*2][1] = r4[2]; b_lo[nf2*2+1][1] = r4[3];
            }
            // term-major: 16 independent accs per pass -> no RAW chains
            #pragma unroll
            for (int mf = 0; mf < 2; mf++)
                #pragma unroll
                for (int nf = 0; nf < 8; nf++)
                    mma16816(acc[mf][nf], a_hi[mf], b_hi[nf]);
            #pragma unroll
            for (int mf = 0; mf < 2; mf++)
                #pragma unroll
                for (int nf = 0; nf < 8; nf++)
                    mma16816(acc[mf][nf], a_hi[mf], b_lo[nf]);
            #pragma unroll
            for (int mf = 0; mf < 2; mf++)
                #pragma unroll
                for (int nf = 0; nf < 8; nf++)
                    mma16816(acc[mf][nf], a_lo[mf], b_hi[nf]);
        }
        p++; if (p == 3) p = 0;
    }
    __syncthreads();   // compute done before epilogue reuses s_red

    // ---- epilogue ----
    const int qr = lane >> 2;
    const int qc = lane & 3;

    #pragma unroll
    for (int mf = 0; mf < 2; mf++) {
        const int vox_lo = wm*32 + mf*16 + qr;
        const int vox_hi = vox_lo + 8;
        const long cell_lo = (((long)b*DS + dz)*DS + dy0 + (vox_lo >> 5))*DS + (vox_lo & 31);
        const long cell_hi = (((long)b*DS + dz)*DS + dy0 + (vox_hi >> 5))*DS + (vox_hi & 31);
        const float m_lo = m2[cell_lo];
        const float m_hi = m2[cell_hi];
        #pragma unroll
        for (int nf = 0; nf < 8; nf++) {
            const int co = wn*64 + nf*8 + qc*2;
            float b0 = bias[co], b1 = bias[co + 1];
            if (HAS_SKIP) { b0 += bias2[co]; b1 += bias2[co + 1]; }
            acc[mf][nf][0] = (acc[mf][nf][0] + b0) * m_lo;
            acc[mf][nf][1] = (acc[mf][nf][1] + b1) * m_lo;
            acc[mf][nf][2] = (acc[mf][nf][2] + b0) * m_hi;
            acc[mf][nf][3] = (acc[mf][nf][3] + b1) * m_hi;
        }
    }

    if (FUSE_LN) {
        float* ps = s_red;            // [128 vox][2 wn]
        float* qs = s_red + 256;
        #pragma unroll
        for (int mf = 0; mf < 2; mf++) {
            float S_lo = 0.f, Q_lo = 0.f, S_hi = 0.f, Q_hi = 0.f;
            #pragma unroll
            for (int nf = 0; nf < 8; nf++) {
                S_lo += acc[mf][nf][0] + acc[mf][nf][1];
                Q_lo += acc[mf][nf][0]*acc[mf][nf][0] + acc[mf][nf][1]*acc[mf][nf][1];
                S_hi += acc[mf][nf][2] + acc[mf][nf][3];
                Q_hi += acc[mf][nf][2]*acc[mf][nf][2] + acc[mf][nf][3]*acc[mf][nf][3];
            }
            #pragma unroll
            for (int o = 1; o < 4; o <<= 1) {
                S_lo += __shfl_xor_sync(0xffffffffu, S_lo, o);
                Q_lo += __shfl_xor_sync(0xffffffffu, Q_lo, o);
                S_hi += __shfl_xor_sync(0xffffffffu, S_hi, o);
                Q_hi += __shfl_xor_sync(0xffffffffu, Q_hi, o);
            }
            if (qc == 0) {
                const int vox_lo = wm*32 + mf*16 + qr;
                ps[vox_lo*2 + wn] = S_lo;  qs[vox_lo*2 + wn] = Q_lo;
                ps[(vox_lo + 8)*2 + wn] = S_hi;  qs[(vox_lo + 8)*2 + wn] = Q_hi;
            }
        }
        __syncthreads();
        #pragma unroll
        for (int mf = 0; mf < 2; mf++) {
            #pragma unroll
            for (int half = 0; half < 2; half++) {
                const int vox = wm*32 + mf*16 + qr + half*8;
                const long cell = (((long)b*DS + dz)*DS + dy0 + (vox >> 5))*DS + (vox & 31);
                const float m = m2[cell];
                const float S = ps[vox*2] + ps[vox*2 + 1];
                const float Q = qs[vox*2] + qs[vox*2 + 1];
                const float mu  = S * (1.f/128.f);
                const float var = Q * (1.f/128.f) - mu*mu;
                const float rsv = rsqrtf(var + 1e-6f);
                #pragma unroll
                for (int nf = 0; nf < 8; nf++) {
                    const int co = wn*64 + nf*8 + qc*2;
                    __nv_bfloat162 vh, vl;
                    #pragma unroll
                    for (int e = 0; e < 2; e++) {
                        const float lnv = (acc[mf][nf][half*2 + e] - mu) * rsv;
                        const float sil = (lnv / (1.f + __expf(-lnv))) * m;
                        const __nv_bfloat16 hi = __float2bfloat16(sil);
                        const __nv_bfloat16 lo = __float2bfloat16(sil - __bfloat162float(hi));
                        if (e == 0) { vh.x = hi; vl.x = lo; } else { vh.y = hi; vl.y = lo; }
                    }
                    *(__nv_bfloat162*)(outhi + cell*C2 + co) = vh;
                    *(__nv_bfloat162*)(outlo + cell*C2 + co) = vl;
                }
            }
        }
    } else {
        #pragma unroll
        for (int mf = 0; mf < 2; mf++) {
            #pragma unroll
            for (int half = 0; half < 2; half++) {
                const int vox = wm*32 + mf*16 + qr + half*8;
                const long cell = (((long)b*DS + dz)*DS + dy0 + (vox >> 5))*DS + (vox & 31);
                #pragma unroll
                for (int nf = 0; nf < 8; nf++) {
                    const int co = wn*64 + nf*8 + qc*2;
                    float2 v;
                    v.x = acc[mf][nf][half*2];
                    v.y = acc[mf][nf][half*2 + 1];
                    *(float2*)(outf + cell*C2 + co) = v;
                }
            }
        }
    }
}

// ---------------- launch ------------------------------------------------------
extern "C" void kernel_launch(void* const* d_in, const int* in_sizes, int n_in,
                              void* d_out, int out_size)
{
    const float* feats = (const float*)d_in[0];
    const void*  mask  = d_in[1];
    const float* gamma1= (const float*)d_in[2];
    const float* beta1 = (const float*)d_in[3];
    const float* w1    = (const float*)d_in[4];
    const float* b1    = (const float*)d_in[5];
    const float* w2    = (const float*)d_in[6];
    const float* b2    = (const float*)d_in[7];
    const float* wsk   = (const float*)d_in[8];
    const float* bsk   = (const float*)d_in[9];
    float* out = (float*)d_out;

    float *p_m2;
    __nv_bfloat16 *p_h1hi, *p_h1lo, *p_xhi, *p_xlo, *p_c1hi, *p_c1lo;
    unsigned char *p_wA1, *p_wA2;
    cudaGetSymbolAddress((void**)&p_m2,   g_m2);
    cudaGetSymbolAddress((void**)&p_h1hi, g_h1hi);
    cudaGetSymbolAddress((void**)&p_h1lo, g_h1lo);
    cudaGetSymbolAddress((void**)&p_xhi,  g_xhi);
    cudaGetSymbolAddress((void**)&p_xlo,  g_xlo);
    cudaGetSymbolAddress((void**)&p_c1hi, g_c1hi);
    cudaGetSymbolAddress((void**)&p_c1lo, g_c1lo);
    cudaGetSymbolAddress((void**)&p_wA1,  g_wA1);
    cudaGetSymbolAddress((void**)&p_wA2,  g_wA2);

    k_detect<<<1, 32>>>((const unsigned int*)mask, in_sizes[1] / 4);
    k_prep_w<<<432, 512>>>(w1, p_wA1, C1);
    k_prep_w<<<864, 512>>>(w2, p_wA2, C2);
    k_prep_skipw<<<16, 512>>>(wsk, p_wA2 + (long)54*32768);
    k_ln_ds<<<NCELL, 256>>>(feats, mask, gamma1, beta1);

    const size_t SMEMSZ = 1024 + 3*65536;             // align pad + 3 stage buffers
    dim3 gC(DS/4, DS, NB);                             // (dy strip, dz, b) = (8,32,4)

    cudaFuncSetAttribute(k_convmma<C1, true, false>,
                         cudaFuncAttributeMaxDynamicSharedMemorySize, (int)SMEMSZ);
    k_convmma<C1, true, false><<<gC, 256, SMEMSZ>>>(p_h1hi, p_h1lo, nullptr, nullptr,
                                                    p_wA1, b1, nullptr, p_m2,
                                                    nullptr, p_c1hi, p_c1lo);

    cudaFuncSetAttribute(k_convmma<C2, false, true>,
                         cudaFuncAttributeMaxDynamicSharedMemorySize, (int)SMEMSZ);
    k_convmma<C2, false, true><<<gC, 256, SMEMSZ>>>(p_c1hi, p_c1lo, p_xhi, p_xlo,
                                                    p_wA2, b2, bsk, p_m2,
                                                    out, nullptr, nullptr);
}

// round 13
// speedup vs baseline: 1.1609x; 1.0000x over previous
#include <cuda_runtime.h>
#include <cuda_bf16.h>
#include <cstdint>

#define NB 4
#define D0 64
#define C1 64
#define C2 128
#define DS 32
#define NCELL (NB*DS*DS*DS)   // 131072

// ---------------- scratch (device globals) ----------------------------------
__device__ float          g_m2  [NCELL];
__device__ __nv_bfloat16  g_h1hi[NCELL*C1];     // conv1 input hi
__device__ __nv_bfloat16  g_h1lo[NCELL*C1];     // conv1 input lo
__device__ __nv_bfloat16  g_xhi [NCELL*C1];     // skip input hi
__device__ __nv_bfloat16  g_xlo [NCELL*C1];     // skip input lo
__device__ __nv_bfloat16  g_c1hi[NCELL*C2];     // conv2 input hi
__device__ __nv_bfloat16  g_c1lo[NCELL*C2];     // conv2 input lo
__device__ unsigned char  g_wA1[27*1*32768];    // conv1 B tiles (hi+lo)
__device__ unsigned char  g_wA2[(27*2+1)*32768];// conv2 B tiles + skip tile (stage 54)
__device__ int            g_mask_mode;

// ---------------- helpers ----------------------------------------------------
__device__ __forceinline__ uint32_t smem_u32(const void* p){
    uint32_t a;
    asm("{ .reg .u64 t; cvta.to.shared.u64 t, %1; cvt.u32.u64 %0, t; }" : "=r"(a) : "l"(p));
    return a;
}
__device__ __forceinline__ void cpa16z(uint32_t dst, const void* src, bool ok){
    int sz = ok ? 16 : 0;
    asm volatile("cp.async.cg.shared.global [%0], [%1], 16, %2;" :: "r"(dst), "l"(src), "r"(sz));
}
__device__ __forceinline__ void cpa_commit(){ asm volatile("cp.async.commit_group;"); }

__device__ __forceinline__ void ldsm4(uint32_t* r, uint32_t addr){
    asm volatile("ldmatrix.sync.aligned.m8n8.x4.shared.b16 {%0,%1,%2,%3}, [%4];"
        : "=r"(r[0]), "=r"(r[1]), "=r"(r[2]), "=r"(r[3]) : "r"(addr));
}
__device__ __forceinline__ void mma16816(float* d, const uint32_t* a, const uint32_t* b){
    asm volatile("mma.sync.aligned.m16n8k16.row.col.f32.bf16.bf16.f32 "
        "{%0,%1,%2,%3}, {%4,%5,%6,%7}, {%8,%9}, {%0,%1,%2,%3};"
        : "+f"(d[0]), "+f"(d[1]), "+f"(d[2]), "+f"(d[3])
        : "r"(a[0]), "r"(a[1]), "r"(a[2]), "r"(a[3]), "r"(b[0]), "r"(b[1]));
}
__device__ __host__ __forceinline__ uint32_t swz(uint32_t row, uint32_t bytecol){
    uint32_t off = row*128u + bytecol;
    return off ^ ((off >> 3) & 0x70u);
}

// ---------------- mask dtype detection ---------------------------------------
__global__ void k_detect(const unsigned int* __restrict__ m, int nwords)
{
    if (threadIdx.x == 0 && blockIdx.x == 0) {
        int mode = 0;
        for (int i = 0; i < nwords; i++) {
            unsigned w = m[i];
            if (w == 0u) continue;
            if (w == 1u)               mode = 0;
            else if (w == 0x3F800000u) mode = 0;
            else                       mode = 2;
            break;
        }
        g_mask_mode = mode;
    }
}
__device__ __forceinline__ bool mask_at(const void* m, long v, int mode)
{
    if (mode == 2) return ((const unsigned char*)m)[v] != 0;
    return ((const unsigned int*)m)[v] != 0u;
}

// ---------------- weight prep: transpose + hi/lo split + smem layout ---------
__global__ void k_prep_w(const float* __restrict__ w, unsigned char* __restrict__ dst, int CIN)
{
    const int total = 27*CIN*128;
    for (int e = blockIdx.x*blockDim.x + threadIdx.x; e < total; e += gridDim.x*blockDim.x) {
        const int t   = e / (CIN*128);
        const int rem = e - t*(CIN*128);
        const int ci  = rem >> 7;
        const int co  = rem & 127;
        const float wv = w[e];
        const __nv_bfloat16 hi = __float2bfloat16(wv);
        const __nv_bfloat16 lo = __float2bfloat16(wv - __bfloat162float(hi));
        const int kc = ci >> 6, cil = ci & 63;
        const int stage = t*(CIN >> 6) + kc;
        const uint32_t off = swz((uint32_t)co, (uint32_t)cil*2u);
        unsigned char* base = dst + (long)stage*32768;
        *(__nv_bfloat16*)(base + off)         = hi;
        *(__nv_bfloat16*)(base + 16384 + off) = lo;
    }
}

// skip weight: wsk [64 ci][128 co] -> stage-54 tile of g_wA2
__global__ void k_prep_skipw(const float* __restrict__ wsk, unsigned char* __restrict__ dst)
{
    const int e = blockIdx.x*blockDim.x + threadIdx.x;
    if (e < 64*128) {
        const int ci = e >> 7;
        const int co = e & 127;
        const float wv = wsk[e];
        const __nv_bfloat16 hi = __float2bfloat16(wv);
        const __nv_bfloat16 lo = __float2bfloat16(wv - __bfloat162float(hi));
        const uint32_t off = swz((uint32_t)co, (uint32_t)ci*2u);
        *(__nv_bfloat16*)(dst + off)         = hi;
        *(__nv_bfloat16*)(dst + 16384 + off) = lo;
    }
}

// ---------------- K1: LN1+affine+SiLU+mask + 2x downsample -------------------
__global__ void __launch_bounds__(256)
k_ln_ds(const float* __restrict__ feats, const void* __restrict__ mask,
        const float* __restrict__ gamma, const float* __restrict__ beta)
{
    const int bid = blockIdx.x;
    const int dx = bid & 31, dy = (bid >> 5) & 31, dz = (bid >> 10) & 31, b = bid >> 15;
    const int tid = threadIdx.x;
    const int s   = tid >> 5;
    const int ln  = tid & 31;
    const int mode = g_mask_mode;

    __shared__ float sh_h[8*64];
    __shared__ float sh_x[8*64];
    __shared__ int   sh_c[8];

    const int z = 2*dz + (s >> 2);
    const int y = 2*dy + ((s >> 1) & 1);
    const int x = 2*dx + (s & 1);
    const long v = (((long)b*D0 + z)*D0 + y)*D0 + x;
    const bool act = mask_at(mask, v, mode);

    const float2 xv = *(const float2*)(feats + v*C1 + ln*2);
    float a = xv.x + xv.y;
    float q = xv.x*xv.x + xv.y*xv.y;
    #pragma unroll
    for (int o = 16; o > 0; o >>= 1) {
        a += __shfl_xor_sync(0xffffffffu, a, o);
        q += __shfl_xor_sync(0xffffffffu, q, o);
    }
    const float mu  = a * (1.f/64.f);
    const float var = q * (1.f/64.f) - mu*mu;
    const float rs  = rsqrtf(var + 1e-6f);

    const float2 g  = *(const float2*)(gamma + ln*2);
    const float2 be = *(const float2*)(beta  + ln*2);
    float h0 = (xv.x - mu)*rs*g.x + be.x;
    float h1 = (xv.y - mu)*rs*g.y + be.y;
    h0 = h0 / (1.f + __expf(-h0));
    h1 = h1 / (1.f + __expf(-h1));

    sh_h[s*64 + ln*2    ] = act ? h0 : 0.f;
    sh_h[s*64 + ln*2 + 1] = act ? h1 : 0.f;
    sh_x[s*64 + ln*2    ] = act ? xv.x : 0.f;
    sh_x[s*64 + ln*2 + 1] = act ? xv.y : 0.f;
    if (ln == 0) sh_c[s] = act ? 1 : 0;
    __syncthreads();

    if (tid < 64) {
        float hs = 0.f, xs = 0.f;
        int cnt = 0;
        #pragma unroll
        for (int k = 0; k < 8; k++) {
            hs += sh_h[k*64 + tid];
            xs += sh_x[k*64 + tid];
            cnt += sh_c[k];
        }
        const float inv = 1.f / (float)max(cnt, 1);
        const float hv = hs * inv;
        const float xm = xs * inv;
        const __nv_bfloat16 hhi = __float2bfloat16(hv);
        const __nv_bfloat16 hlo = __float2bfloat16(hv - __bfloat162float(hhi));
        const __nv_bfloat16 xhi = __float2bfloat16(xm);
        const __nv_bfloat16 xlo = __float2bfloat16(xm - __bfloat162float(xhi));
        g_h1hi[(long)bid*C1 + tid] = hhi;
        g_h1lo[(long)bid*C1 + tid] = hlo;
        g_xhi [(long)bid*C1 + tid] = xhi;
        g_xlo [(long)bid*C1 + tid] = xlo;
        if (tid == 0) g_m2[bid] = (cnt > 0) ? 1.f : 0.f;
    }
}

// ---------------- conv via mma.sync (split-bf16 3-term) ----------------------
// Block 256 thr / 8 warps. Tile: 128 voxels (4 dy rows x 32 x) x 128 cout.
// Triple-buffered, ONE barrier per stage (prefetch issued post-barrier).
// MMA order is term-major: 3 passes over 16 independent acc fragments.
template<int CIN, bool FUSE_LN, bool HAS_SKIP>
__global__ void __launch_bounds__(256, 1)
k_convmma(const __nv_bfloat16* __restrict__ inhi, const __nv_bfloat16* __restrict__ inlo,
          const __nv_bfloat16* __restrict__ skhi, const __nv_bfloat16* __restrict__ sklo,
          const unsigned char* __restrict__ wA, const float* __restrict__ bias,
          const float* __restrict__ bias2, const float* __restrict__ m2,
          float* __restrict__ outf,
          __nv_bfloat16* __restrict__ outhi, __nv_bfloat16* __restrict__ outlo)
{
    constexpr int NKC = CIN / 64;
    constexpr int NS  = 27 * NKC;
    constexpr int NST = NS + (HAS_SKIP ? 1 : 0);

    extern __shared__ char smraw[];
    const uint32_t sb0 = smem_u32(smraw);
    const uint32_t BUF = (sb0 + 1023) & ~1023u;
    float* s_red = (float*)(smraw + (BUF - sb0));

    const int tid  = threadIdx.x;
    const int lane = tid & 31;
    const int w    = tid >> 5;
    const int wm   = w >> 1;          // 0..3
    const int wn   = w & 1;           // 0..1
    const int dy0  = blockIdx.x * 4;
    const int dz   = blockIdx.y;
    const int b    = blockIdx.z;

    float acc[2][8][4];
    #pragma unroll
    for (int mf = 0; mf < 2; mf++)
        #pragma unroll
        for (int nf = 0; nf < 8; nf++)
            #pragma unroll
            for (int k = 0; k < 4; k++) acc[mf][nf][k] = 0.f;

    // ---- stage copier ----
    auto stage_copy = [&](int s, int p){
        const uint32_t base = BUF + (uint32_t)p * 65536u;
        if (HAS_SKIP && s == NS) {
            #pragma unroll
            for (int i = 0; i < 16; i++) {
                const int flat = tid + i*256;
                if (flat < 2048) {
                    const int half = flat >> 10;
                    const int f    = flat & 1023;
                    const int vox  = f >> 3;
                    const int seg  = f & 7;
                    const long cell = (((long)b*DS + dz)*DS + dy0 + (vox >> 5))*DS + (vox & 31);
                    const __nv_bfloat16* src =
                        (half ? sklo : skhi) + cell*C1 + seg*8;
                    cpa16z(base + (uint32_t)half*16384u + swz((uint32_t)vox, (uint32_t)seg*16u),
                           src, true);
                } else {
                    const int f = flat - 2048;
                    cpa16z(base + 32768u + (uint32_t)f*16u,
                           wA + (long)s*32768 + (long)f*16, true);
                }
            }
            cpa_commit();
            return;
        }
        const int t  = s / NKC;
        const int kc = s - t*NKC;
        const int kd = t / 9;
        const int r9 = t - kd*9;
        const int kh = r9 / 3;
        const int kw = r9 - kh*3;
        const int z  = dz + kd - 1;
        const bool zok = (unsigned)z < DS;
        #pragma unroll
        for (int i = 0; i < 16; i++) {
            const int flat = tid + i*256;            // 0..4095 (16B units)
            if (flat < 2048) {                       // A input tiles (hi, lo)
                const int half = flat >> 10;
                const int f    = flat & 1023;
                const int vox  = f >> 3;
                const int seg  = f & 7;
                const int r    = vox >> 5;
                const int x    = vox & 31;
                const int y    = dy0 + r + kh - 1;
                const int xx   = x + kw - 1;
                const bool ok  = zok && ((unsigned)y < DS) && ((unsigned)xx < DS);
                const long cell = ok ? ((((long)b*DS + z)*DS + y)*DS + xx) : 0;
                const __nv_bfloat16* src =
                    (half ? inlo : inhi) + cell*CIN + kc*64 + seg*8;
                cpa16z(base + (uint32_t)half*16384u + swz((uint32_t)vox, (uint32_t)seg*16u),
                       src, ok);
            } else {                                  // B weight tiles
                const int f = flat - 2048;
                cpa16z(base + 32768u + (uint32_t)f*16u,
                       wA + (long)s*32768 + (long)f*16, true);
            }
        }
        cpa_commit();
    };

    stage_copy(0, 0);
    if (NST > 1) stage_copy(1, 1);

    int p = 0;   // buffer index of stage s
    for (int s = 0; s < NST; s++) {
        // complete stage s's copy (allow s+1 to stay pending)
        if (s < NST - 1) asm volatile("cp.async.wait_group 1;");
        else             asm volatile("cp.async.wait_group 0;");
        __syncthreads();   // all warps finished compute s-1; copies of s visible

        // prefetch s+2 into buffer of s-1 (safe: post-barrier)
        if (s + 2 < NST) {
            int p2 = p + 2; if (p2 >= 3) p2 -= 3;
            stage_copy(s + 2, p2);
        }

        const uint32_t Ab = BUF + (uint32_t)p*65536u;
        const uint32_t Bb = Ab + 32768u;

        #pragma unroll
        for (int ks = 0; ks < 4; ks++) {
            const uint32_t colb = (uint32_t)(ks*16 + ((lane >> 4) & 1)*8) * 2u;
            uint32_t a_hi[2][4], a_lo[2][4];
            #pragma unroll
            for (int mf = 0; mf < 2; mf++) {
                const uint32_t row = (uint32_t)(wm*32 + mf*16 + (lane & 15));
                const uint32_t ad = Ab + swz(row, colb);
                ldsm4(a_hi[mf], ad);
                ldsm4(a_lo[mf], ad + 16384u);
            }
            uint32_t b_hi[8][2], b_lo[8][2];
            #pragma unroll
            for (int nf2 = 0; nf2 < 4; nf2++) {
                const uint32_t row = (uint32_t)(wn*64 + nf2*16 + (lane & 15));
                const uint32_t ad = Bb + swz(row, colb);
                uint32_t r4[4];
                ldsm4(r4, ad);
                b_hi[nf2*2][0] = r4[0]; b_hi[nf2*2+1][0] = r4[1];
                b_hi[nf2*2][1] = r4[2]; b_hi[nf2*2+1][1] = r4[3];
                ldsm4(r4, ad + 16384u);
                b_lo[nf2*2][0] = r4[0]; b_lo[nf2*2+1][0] = r4[1];
                b_lo[nf2*2][1] = r4[2]; b_lo[nf2*2+1][1] = r4[3];
            }
            // term-major: 16 independent accs per pass -> no RAW chains
            #pragma unroll
            for (int mf = 0; mf < 2; mf++)
                #pragma unroll
                for (int nf = 0; nf < 8; nf++)
                    mma16816(acc[mf][nf], a_hi[mf], b_hi[nf]);
            #pragma unroll
            for (int mf = 0; mf < 2; mf++)
                #pragma unroll
                for (int nf = 0; nf < 8; nf++)
                    mma16816(acc[mf][nf], a_hi[mf], b_lo[nf]);
            #pragma unroll
            for (int mf = 0; mf < 2; mf++)
                #pragma unroll
                for (int nf = 0; nf < 8; nf++)
                    mma16816(acc[mf][nf], a_lo[mf], b_hi[nf]);
        }
        p++; if (p == 3) p = 0;
    }
    __syncthreads();   // compute done before epilogue reuses s_red

    // ---- epilogue ----
    const int qr = lane >> 2;
    const int qc = lane & 3;

    #pragma unroll
    for (int mf = 0; mf < 2; mf++) {
        const int vox_lo = wm*32 + mf*16 + qr;
        const int vox_hi = vox_lo + 8;
        const long cell_lo = (((long)b*DS + dz)*DS + dy0 + (vox_lo >> 5))*DS + (vox_lo & 31);
        const long cell_hi = (((long)b*DS + dz)*DS + dy0 + (vox_hi >> 5))*DS + (vox_hi & 31);
        const float m_lo = m2[cell_lo];
        const float m_hi = m2[cell_hi];
        #pragma unroll
        for (int nf = 0; nf < 8; nf++) {
            const int co = wn*64 + nf*8 + qc*2;
            float b0 = bias[co], b1 = bias[co + 1];
            if (HAS_SKIP) { b0 += bias2[co]; b1 += bias2[co + 1]; }
            acc[mf][nf][0] = (acc[mf][nf][0] + b0) * m_lo;
            acc[mf][nf][1] = (acc[mf][nf][1] + b1) * m_lo;
            acc[mf][nf][2] = (acc[mf][nf][2] + b0) * m_hi;
            acc[mf][nf][3] = (acc[mf][nf][3] + b1) * m_hi;
        }
    }

    if (FUSE_LN) {
        float* ps = s_red;            // [128 vox][2 wn]
        float* qs = s_red + 256;
        #pragma unroll
        for (int mf = 0; mf < 2; mf++) {
            float S_lo = 0.f, Q_lo = 0.f, S_hi = 0.f, Q_hi = 0.f;
            #pragma unroll
            for (int nf = 0; nf < 8; nf++) {
                S_lo += acc[mf][nf][0] + acc[mf][nf][1];
                Q_lo += acc[mf][nf][0]*acc[mf][nf][0] + acc[mf][nf][1]*acc[mf][nf][1];
                S_hi += acc[mf][nf][2] + acc[mf][nf][3];
                Q_hi += acc[mf][nf][2]*acc[mf][nf][2] + acc[mf][nf][3]*acc[mf][nf][3];
            }
            #pragma unroll
            for (int o = 1; o < 4; o <<= 1) {
                S_lo += __shfl_xor_sync(0xffffffffu, S_lo, o);
                Q_lo += __shfl_xor_sync(0xffffffffu, Q_lo, o);
                S_hi += __shfl_xor_sync(0xffffffffu, S_hi, o);
                Q_hi += __shfl_xor_sync(0xffffffffu, Q_hi, o);
            }
            if (qc == 0) {
                const int vox_lo = wm*32 + mf*16 + qr;
                ps[vox_lo*2 + wn] = S_lo;  qs[vox_lo*2 + wn] = Q_lo;
                ps[(vox_lo + 8)*2 + wn] = S_hi;  qs[(vox_lo + 8)*2 + wn] = Q_hi;
            }
        }
        __syncthreads();
        #pragma unroll
        for (int mf = 0; mf < 2; mf++) {
            #pragma unroll
            for (int half = 0; half < 2; half++) {
                const int vox = wm*32 + mf*16 + qr + half*8;
                const long cell = (((long)b*DS + dz)*DS + dy0 + (vox >> 5))*DS + (vox & 31);
                const float m = m2[cell];
                const float S = ps[vox*2] + ps[vox*2 + 1];
                const float Q = qs[vox*2] + qs[vox*2 + 1];
                const float mu  = S * (1.f/128.f);
                const float var = Q * (1.f/128.f) - mu*mu;
                const float rsv = rsqrtf(var + 1e-6f);
                #pragma unroll
                for (int nf = 0; nf < 8; nf++) {
                    const int co = wn*64 + nf*8 + qc*2;
                    __nv_bfloat162 vh, vl;
                    #pragma unroll
                    for (int e = 0; e < 2; e++) {
                        const float lnv = (acc[mf][nf][half*2 + e] - mu) * rsv;
                        const float sil = (lnv / (1.f + __expf(-lnv))) * m;
                        const __nv_bfloat16 hi = __float2bfloat16(sil);
                        const __nv_bfloat16 lo = __float2bfloat16(sil - __bfloat162float(hi));
                        if (e == 0) { vh.x = hi; vl.x = lo; } else { vh.y = hi; vl.y = lo; }
                    }
                    *(__nv_bfloat162*)(outhi + cell*C2 + co) = vh;
                    *(__nv_bfloat162*)(outlo + cell*C2 + co) = vl;
                }
            }
        }
    } else {
        #pragma unroll
        for (int mf = 0; mf < 2; mf++) {
            #pragma unroll
            for (int half = 0; half < 2; half++) {
                const int vox = wm*32 + mf*16 + qr + half*8;
                const long cell = (((long)b*DS + dz)*DS + dy0 + (vox >> 5))*DS + (vox & 31);
                #pragma unroll
                for (int nf = 0; nf < 8; nf++) {
                    const int co = wn*64 + nf*8 + qc*2;
                    float2 v;
                    v.x = acc[mf][nf][half*2];
                    v.y = acc[mf][nf][half*2 + 1];
                    *(float2*)(outf + cell*C2 + co) = v;
                }
            }
        }
    }
}

// ---------------- launch ------------------------------------------------------
extern "C" void kernel_launch(void* const* d_in, const int* in_sizes, int n_in,
                              void* d_out, int out_size)
{
    const float* feats = (const float*)d_in[0];
    const void*  mask  = d_in[1];
    const float* gamma1= (const float*)d_in[2];
    const float* beta1 = (const float*)d_in[3];
    const float* w1    = (const float*)d_in[4];
    const float* b1    = (const float*)d_in[5];
    const float* w2    = (const float*)d_in[6];
    const float* b2    = (const float*)d_in[7];
    const float* wsk   = (const float*)d_in[8];
    const float* bsk   = (const float*)d_in[9];
    float* out = (float*)d_out;

    float *p_m2;
    __nv_bfloat16 *p_h1hi, *p_h1lo, *p_xhi, *p_xlo, *p_c1hi, *p_c1lo;
    unsigned char *p_wA1, *p_wA2;
    cudaGetSymbolAddress((void**)&p_m2,   g_m2);
    cudaGetSymbolAddress((void**)&p_h1hi, g_h1hi);
    cudaGetSymbolAddress((void**)&p_h1lo, g_h1lo);
    cudaGetSymbolAddress((void**)&p_xhi,  g_xhi);
    cudaGetSymbolAddress((void**)&p_xlo,  g_xlo);
    cudaGetSymbolAddress((void**)&p_c1hi, g_c1hi);
    cudaGetSymbolAddress((void**)&p_c1lo, g_c1lo);
    cudaGetSymbolAddress((void**)&p_wA1,  g_wA1);
    cudaGetSymbolAddress((void**)&p_wA2,  g_wA2);

    k_detect<<<1, 32>>>((const unsigned int*)mask, in_sizes[1] / 4);
    k_prep_w<<<432, 512>>>(w1, p_wA1, C1);
    k_prep_w<<<864, 512>>>(w2, p_wA2, C2);
    k_prep_skipw<<<16, 512>>>(wsk, p_wA2 + (long)54*32768);
    k_ln_ds<<<NCELL, 256>>>(feats, mask, gamma1, beta1);

    const size_t SMEMSZ = 1024 + 3*65536;             // align pad + 3 stage buffers
    dim3 gC(DS/4, DS, NB);                             // (dy strip, dz, b) = (8,32,4)

    cudaFuncSetAttribute(k_convmma<C1, true, false>,
                         cudaFuncAttributeMaxDynamicSharedMemorySize, (int)SMEMSZ);
    k_convmma<C1, true, false><<<gC, 256, SMEMSZ>>>(p_h1hi, p_h1lo, nullptr, nullptr,
                                                    p_wA1, b1, nullptr, p_m2,
                                                    nullptr, p_c1hi, p_c1lo);

    cudaFuncSetAttribute(k_convmma<C2, false, true>,
                         cudaFuncAttributeMaxDynamicSharedMemorySize, (int)SMEMSZ);
    k_convmma<C2, false, true><<<gC, 256, SMEMSZ>>>(p_c1hi, p_c1lo, p_xhi, p_xlo,
                                                    p_wA2, b2, bsk, p_m2,
                                                    out, nullptr, nullptr);
}